// round 14
// baseline (speedup 1.0000x reference)
#include <cuda_runtime.h>
#include <cuda_bf16.h>
#include <cstdint>
#include <math.h>

// Problem constants
#define NN_   3072      // nodes
#define DD    256       // hidden dim
#define OD    512       // output dim
#define HN    8         // heads
#define DHD   32        // head dim
#define EN    49152     // edges
#define NETN  5         // edge types
#define NCN   8         // communities
#define MAXC  640       // max community size (actual ~384)
#define QS_   (3 * DD)

// local attention tiling
#define RPB   16        // rows per block
#define CTL   16        // cols per tile
#define QPITCH 258      // smem row pitch (floats), conflict-free
#define EMAX  64        // max same-community edges per row

// ---------------- device scratch (static; no allocation) ----------------
__device__ __align__(16) float g_h[NN_ * DD];
__device__ __align__(16) float g_qkv[NN_ * QS_];          // fused Q|K|V fp32 (local layers)
__device__ __align__(16) float g_slab[2 * NN_ * QS_];     // split-K partial outputs
__device__ __align__(16) float g_bpack[4 * QS_];          // packed QKV biases

__device__ __align__(16) __nv_bfloat16 g_xh[NN_ * DD],  g_xl[NN_ * DD];
__device__ __align__(16) __nv_bfloat16 g_qh[NN_ * DD];
__device__ __align__(16) __nv_bfloat16 g_kh[NN_ * DD];
__device__ __align__(16) __nv_bfloat16 g_vth[DD * NN_];                    // V^T
__device__ __align__(16) __nv_bfloat16 g_Sb[(size_t)NN_ * NN_];            // S -> P in place
__device__ __align__(16) __nv_bfloat16 g_wqh[4 * QS_ * DD], g_wql[4 * QS_ * DD];
__device__ __align__(16) __nv_bfloat16 g_owh[4 * DD * DD],  g_owl[4 * DD * DD];
__device__ __align__(16) __nv_bfloat16 g_outwh[OD * DD],    g_outwl[OD * DD];

__device__ int g_order[NN_];
__device__ int g_inv[NN_];
__device__ int g_cstart[NCN + 1];
__device__ int g_deg[NN_];
__device__ int g_rowptr[NN_ + 1];
__device__ int g_cur[NN_];
__device__ int g_eidx[EN];

// ==================== small helpers ====================

__device__ __forceinline__ uint32_t smem_u32(const void* p) {
    uint32_t a;
    asm("{ .reg .u64 t; cvta.to.shared.u64 t, %1; cvt.u32.u64 %0, t; }" : "=r"(a) : "l"(p));
    return a;
}

__device__ __forceinline__ void cpa16(uint32_t s, const void* g) {
    asm volatile("cp.async.cg.shared.global [%0], [%1], 16;\n" :: "r"(s), "l"(g) : "memory");
}

__device__ __forceinline__ void split1(float x, __nv_bfloat16& h, __nv_bfloat16& l) {
    h = __float2bfloat16(x);
    l = __float2bfloat16(x - __bfloat162float(h));
}

__device__ __forceinline__ void ldsm_x4(uint32_t* r, uint32_t addr) {
    asm volatile("ldmatrix.sync.aligned.m8n8.x4.shared.b16 {%0,%1,%2,%3}, [%4];"
        : "=r"(r[0]), "=r"(r[1]), "=r"(r[2]), "=r"(r[3]) : "r"(addr));
}

// ==================== setup kernels ====================

// also zeroes g_deg
__global__ void build_perm2(const int* __restrict__ cid) {
    __shared__ int cnt[NCN][1024];
    int t = threadIdx.x;
    for (int i = t; i < NN_; i += 1024) g_deg[i] = 0;
    int base = t * 3;
    int c0 = cid[base], c1 = cid[base + 1], c2 = cid[base + 2];
    int loc[NCN];
#pragma unroll
    for (int c = 0; c < NCN; c++) loc[c] = 0;
    loc[c0]++; loc[c1]++; loc[c2]++;
#pragma unroll
    for (int c = 0; c < NCN; c++) cnt[c][t] = loc[c];
    __syncthreads();
    for (int off = 1; off < 1024; off <<= 1) {
        int v[NCN];
#pragma unroll
        for (int c = 0; c < NCN; c++) v[c] = (t >= off) ? cnt[c][t - off] : 0;
        __syncthreads();
#pragma unroll
        for (int c = 0; c < NCN; c++) cnt[c][t] += v[c];
        __syncthreads();
    }
    if (t == 0) {
        int a = 0;
        for (int c = 0; c < NCN; c++) { g_cstart[c] = a; a += cnt[c][1023]; }
        g_cstart[NCN] = a;
    }
    __syncthreads();
    int excl[NCN];
#pragma unroll
    for (int c = 0; c < NCN; c++) excl[c] = (t > 0) ? cnt[c][t - 1] : 0;
#pragma unroll
    for (int i = 0; i < 3; i++) {
        int n = base + i;
        int c = cid[n];
        int p = g_cstart[c] + excl[c];
        excl[c]++;
        g_order[p] = n;
        g_inv[n] = p;
    }
}

__global__ void count_deg(const int* __restrict__ ei) {
    int e = blockIdx.x * 256 + threadIdx.x;
    if (e < EN) atomicAdd(&g_deg[ei[e]], 1);
}

__global__ void scan_deg() {
    __shared__ int s[1024];
    int t = threadIdx.x;
    int b = t * 3;
    int d0 = g_deg[b], d1 = g_deg[b + 1], d2 = g_deg[b + 2];
    s[t] = d0 + d1 + d2;
    __syncthreads();
    for (int off = 1; off < 1024; off <<= 1) {
        int v = (t >= off) ? s[t - off] : 0;
        __syncthreads();
        s[t] += v;
        __syncthreads();
    }
    int excl = (t > 0) ? s[t - 1] : 0;
    g_rowptr[b] = excl;       g_cur[b]     = excl;
    g_rowptr[b + 1] = excl + d0; g_cur[b + 1] = excl + d0;
    g_rowptr[b + 2] = excl + d0 + d1; g_cur[b + 2] = excl + d0 + d1;
    if (t == 1023) g_rowptr[NN_] = s[1023];
}

__global__ void scatter_edges(const int* __restrict__ ei) {
    int e = blockIdx.x * 256 + threadIdx.x;
    if (e >= EN) return;
    int s = ei[e];
    int p = atomicAdd(&g_cur[s], 1);
    g_eidx[p] = e;
}

// fused weight prep
#define PW_R0 (4 * QS_ * DD)
#define PW_R1 (4 * DD * DD)
#define PW_R2 (OD * DD)
#define PW_R3 (4 * QS_)
__global__ void prep_weights(
    const float* __restrict__ lqw, const float* __restrict__ lkw, const float* __restrict__ lvw,
    const float* __restrict__ gqw, const float* __restrict__ gkw, const float* __restrict__ gvw,
    const float* __restrict__ low, const float* __restrict__ gow, const float* __restrict__ outw,
    const float* __restrict__ lqb, const float* __restrict__ lkb, const float* __restrict__ lvb,
    const float* __restrict__ gqb, const float* __restrict__ gkb, const float* __restrict__ gvb)
{
    int i = blockIdx.x * 256 + threadIdx.x;
    if (i < PW_R0) {
        int l = i / (QS_ * DD);
        int rem = i - l * (QS_ * DD);
        int n = rem / DD;
        int k = rem - n * DD;
        int sel = n >> 8;
        int nn = n & (DD - 1);
        const float* qw = (l < 2) ? lqw : gqw;
        const float* kw = (l < 2) ? lkw : gkw;
        const float* vw = (l < 2) ? lvw : gvw;
        int loff = ((l < 2) ? l : (l - 2)) * DD * DD;
        const float* src = (sel == 0) ? qw : (sel == 1) ? kw : vw;
        split1(src[loff + k * DD + nn], g_wqh[i], g_wql[i]);
        return;
    }
    i -= PW_R0;
    if (i < PW_R1) {
        int l = i / (DD * DD);
        int rem = i - l * (DD * DD);
        int n = rem / DD, k = rem - n * DD;
        const float* src = (l < 2) ? low : gow;
        int loff = ((l < 2) ? l : (l - 2)) * DD * DD;
        split1(src[loff + k * DD + n], g_owh[l * DD * DD + rem], g_owl[l * DD * DD + rem]);
        return;
    }
    i -= PW_R1;
    if (i < PW_R2) {
        int n = i / DD, k = i - n * DD;
        split1(outw[k * OD + n], g_outwh[i], g_outwl[i]);
        return;
    }
    i -= PW_R2;
    if (i < PW_R3) {
        int l = i / QS_;
        int n = i - l * QS_;
        int sel = n >> 8;
        int nn = n & (DD - 1);
        const float* qb = (l < 2) ? lqb : gqb;
        const float* kb = (l < 2) ? lkb : gkb;
        const float* vb = (l < 2) ? lvb : gvb;
        int loff = ((l < 2) ? l : (l - 2)) * DD;
        const float* src = (sel == 0) ? qb : (sel == 1) ? kb : vb;
        g_bpack[i] = src[loff + nn];
    }
}

// ==================== fused elementwise kernels ====================

__global__ void embed_split(const float* __restrict__ x, const float* __restrict__ w,
                            const float* __restrict__ b, const float* __restrict__ pos) {
    int i = blockIdx.x * 256 + threadIdx.x;
    int d = i & (DD - 1);
    float hh = x[i >> 8] * w[d] + b[d];
    g_h[i] = hh;
    split1(hh + pos[i], g_xh[i], g_xl[i]);
}

// xh/xl = split(sum of 2 PV slabs)
__global__ void reduce_pv_split() {
    int i = blockIdx.x * 256 + threadIdx.x;
    float s = g_slab[i] + g_slab[NN_ * DD + i];
    split1(s, g_xh[i], g_xl[i]);
}

// h = LayerNorm(h + sum2slabs + bias)*g + b ; xh/xl = split(h [+ pos])
__global__ void ln_res_f(const float* __restrict__ gam, const float* __restrict__ bet,
                         const float* __restrict__ pos, const float* __restrict__ bias) {
    int w = threadIdx.x >> 5, lane = threadIdx.x & 31;
    int n = blockIdx.x * 8 + w;
    const int base = n * DD;
    float v[8];
    float s = 0.f;
#pragma unroll
    for (int i = 0; i < 8; i++) {
        int d = i * 32 + lane;
        int idx = base + d;
        float t = g_slab[idx] + g_slab[NN_ * DD + idx] + bias[d];
        v[i] = g_h[idx] + t;
        s += v[i];
    }
#pragma unroll
    for (int o = 16; o; o >>= 1) s += __shfl_xor_sync(0xffffffffu, s, o);
    float mean = s * (1.f / DD);
    float vs = 0.f;
#pragma unroll
    for (int i = 0; i < 8; i++) { float d = v[i] - mean; vs += d * d; }
#pragma unroll
    for (int o = 16; o; o >>= 1) vs += __shfl_xor_sync(0xffffffffu, vs, o);
    float r = rsqrtf(vs * (1.f / DD) + 1e-5f);
#pragma unroll
    for (int i = 0; i < 8; i++) {
        int d = i * 32 + lane;
        float y = (v[i] - mean) * r * gam[d] + bet[d];
        g_h[base + d] = y;
        float z = pos ? (y + pos[base + d]) : y;
        split1(z, g_xh[base + d], g_xl[base + d]);
    }
}

// ==================== mma.sync GEMM: 128x64 tile (unchanged from R13) ====================

#define KCH  32
#define SSTR 40
#define TILEA (128 * SSTR * 2)
#define TILEB64 (64 * SSTR * 2)
#define STG3 (2 * TILEA + 2 * TILEB64)
#define STG1 (TILEA + TILEB64)

__device__ __forceinline__ void mma16816(float* d, const uint32_t* a, const uint32_t* b) {
    asm volatile(
        "mma.sync.aligned.m16n8k16.row.col.f32.bf16.bf16.f32 "
        "{%0,%1,%2,%3}, {%4,%5,%6,%7}, {%8,%9}, {%0,%1,%2,%3};\n"
        : "+f"(d[0]), "+f"(d[1]), "+f"(d[2]), "+f"(d[3])
        : "r"(a[0]), "r"(a[1]), "r"(a[2]), "r"(a[3]), "r"(b[0]), "r"(b[1]));
}

template<int PASSES, bool SLAB, bool BF16OUT, bool QKVB>
__global__ void __launch_bounds__(256, 2) mma_gemm_nt(
    const __nv_bfloat16* __restrict__ Ah, const __nv_bfloat16* __restrict__ Al, int lda,
    const __nv_bfloat16* __restrict__ Bh, const __nv_bfloat16* __restrict__ Bl, int ldb,
    const float* __restrict__ bias, void* __restrict__ Cv, int ldc,
    int K, float alpha, int kchunk, size_t slabstride)
{
    extern __shared__ char dsm[];
    const int STAGE = (PASSES == 3) ? STG3 : STG1;
    const uint32_t OFF_BH = (PASSES == 3) ? 2 * TILEA : TILEA;
    const uint32_t sbase = smem_u32(dsm);

    const int tid = threadIdx.x;
    const int lane = tid & 31;
    const int wid = tid >> 5;
    const int warp_m = wid & 3;
    const int warp_n = wid >> 2;
    const int bm = blockIdx.y * 128, bn = blockIdx.x * 64;
    const int kbeg = blockIdx.z * kchunk;
    int kend = kbeg + kchunk;
    if (kend > K) kend = K;
    const int nch = (kend - kbeg) / KCH;

    const int r0 = tid >> 2;
    const int c4 = tid & 3;
    const uint32_t soA0 = (uint32_t)(r0 * SSTR + c4 * 8) * 2;
    const uint32_t soA1 = (uint32_t)((r0 + 64) * SSTR + c4 * 8) * 2;
    const uint32_t soB  = soA0;

    const uint32_t lane7 = lane & 7;
    const uint32_t aoff0 = (uint32_t)((warp_m * 32 + ((lane >> 3) & 1) * 8 + lane7) * SSTR) * 2
                         + (uint32_t)(lane >> 4) * 16;
    const uint32_t aoff1 = aoff0 + (uint32_t)(16 * SSTR) * 2;
    uint32_t boff[2];
#pragma unroll
    for (int jj = 0; jj < 2; jj++)
        boff[jj] = (uint32_t)((warp_n * 32 + jj * 16 + (lane >> 4) * 8 + lane7) * SSTR) * 2
                 + (uint32_t)((lane >> 3) & 1) * 16;

    auto issue = [&](int ch) {
        int k0 = kbeg + ch * KCH;
        uint32_t st = sbase + (uint32_t)(ch & 1) * STAGE;
        const __nv_bfloat16* a0 = Ah + (size_t)(bm + r0) * lda + k0 + c4 * 8;
        const __nv_bfloat16* b0 = Bh + (size_t)(bn + r0) * ldb + k0 + c4 * 8;
        cpa16(st + soA0, a0);
        cpa16(st + soA1, a0 + (size_t)64 * lda);
        cpa16(st + OFF_BH + soB, b0);
        if (PASSES == 3) {
            const __nv_bfloat16* a1 = Al + (size_t)(bm + r0) * lda + k0 + c4 * 8;
            const __nv_bfloat16* b1 = Bl + (size_t)(bn + r0) * ldb + k0 + c4 * 8;
            cpa16(st + TILEA + soA0, a1);
            cpa16(st + TILEA + soA1, a1 + (size_t)64 * lda);
            cpa16(st + OFF_BH + TILEB64 + soB, b1);
        }
        asm volatile("cp.async.commit_group;\n" ::: "memory");
    };

    float acc[2][4][4];
#pragma unroll
    for (int i = 0; i < 2; i++)
#pragma unroll
        for (int j = 0; j < 4; j++)
#pragma unroll
            for (int q = 0; q < 4; q++) acc[i][j][q] = 0.f;

    issue(0);
    for (int ch = 0; ch < nch; ch++) {
        if (ch + 1 < nch) {
            issue(ch + 1);
            asm volatile("cp.async.wait_group 1;\n" ::: "memory");
        } else {
            asm volatile("cp.async.wait_group 0;\n" ::: "memory");
        }
        __syncthreads();

        const uint32_t stage = sbase + (uint32_t)(ch & 1) * STAGE;

#pragma unroll
        for (int ks = 0; ks < 2; ks++) {
            const uint32_t kso = (uint32_t)ks * 32;
            uint32_t a0[4], a1[4], bh[2][4];
            ldsm_x4(a0, stage + aoff0 + kso);
            ldsm_x4(a1, stage + aoff1 + kso);
            ldsm_x4(bh[0], stage + OFF_BH + boff[0] + kso);
            ldsm_x4(bh[1], stage + OFF_BH + boff[1] + kso);
#pragma unroll
            for (int jj = 0; jj < 2; jj++) {
                mma16816(acc[0][2 * jj],     a0, bh[jj]);
                mma16816(acc[1][2 * jj],     a1, bh[jj]);
                mma16816(acc[0][2 * jj + 1], a0, bh[jj] + 2);
                mma16816(acc[1][2 * jj + 1], a1, bh[jj] + 2);
            }
            if (PASSES == 3) {
                uint32_t bl[2][4];
                ldsm_x4(bl[0], stage + OFF_BH + TILEB64 + boff[0] + kso);
                ldsm_x4(bl[1], stage + OFF_BH + TILEB64 + boff[1] + kso);
#pragma unroll
                for (int jj = 0; jj < 2; jj++) {
                    mma16816(acc[0][2 * jj],     a0, bl[jj]);
                    mma16816(acc[1][2 * jj],     a1, bl[jj]);
                    mma16816(acc[0][2 * jj + 1], a0, bl[jj] + 2);
                    mma16816(acc[1][2 * jj + 1], a1, bl[jj] + 2);
                }
                uint32_t al0[4], al1[4];
                ldsm_x4(al0, stage + TILEA + aoff0 + kso);
                ldsm_x4(al1, stage + TILEA + aoff1 + kso);
#pragma unroll
                for (int jj = 0; jj < 2; jj++) {
                    mma16816(acc[0][2 * jj],     al0, bh[jj]);
                    mma16816(acc[1][2 * jj],     al1, bh[jj]);
                    mma16816(acc[0][2 * jj + 1], al0, bh[jj] + 2);
                    mma16816(acc[1][2 * jj + 1], al1, bh[jj] + 2);
                }
            }
        }
        __syncthreads();
    }

    float* Cf = (float*)Cv;
    __nv_bfloat16* Cb = (__nv_bfloat16*)Cv;
    if (SLAB) Cf += (size_t)blockIdx.z * slabstride;
    const int row = bm + warp_m * 32 + (lane >> 2);
    const int col = bn + warp_n * 32 + (lane & 3) * 2;
#pragma unroll
    for (int i = 0; i < 2; i++) {
#pragma unroll
        for (int j = 0; j < 4; j++) {
            int r = row + i * 16;
            int c = col + j * 8;
            float d0 = alpha * acc[i][j][0];
            float d1 = alpha * acc[i][j][1];
            float d2 = alpha * acc[i][j][2];
            float d3 = alpha * acc[i][j][3];
            if (QKVB) {
                float b0 = bias[c], b1 = bias[c + 1];
                d0 += b0; d1 += b1; d2 += b0; d3 += b1;
                __nv_bfloat16 v00 = __float2bfloat16(d0);
                __nv_bfloat16 v01 = __float2bfloat16(d1);
                __nv_bfloat16 v10 = __float2bfloat16(d2);
                __nv_bfloat16 v11 = __float2bfloat16(d3);
                int sel = c >> 8;
                int cc = c & (DD - 1);
                if (sel == 0) {
                    *(__nv_bfloat162*)&g_qh[r * DD + cc] = {v00, v01};
                    *(__nv_bfloat162*)&g_qh[(r + 8) * DD + cc] = {v10, v11};
                } else if (sel == 1) {
                    *(__nv_bfloat162*)&g_kh[r * DD + cc] = {v00, v01};
                    *(__nv_bfloat162*)&g_kh[(r + 8) * DD + cc] = {v10, v11};
                } else {
                    g_vth[(size_t)cc * NN_ + r] = v00;
                    g_vth[(size_t)(cc + 1) * NN_ + r] = v01;
                    g_vth[(size_t)cc * NN_ + r + 8] = v10;
                    g_vth[(size_t)(cc + 1) * NN_ + r + 8] = v11;
                }
            } else if (BF16OUT) {
                __nv_bfloat162 v0, v1;
                v0.x = __float2bfloat16(d0); v0.y = __float2bfloat16(d1);
                v1.x = __float2bfloat16(d2); v1.y = __float2bfloat16(d3);
                *(__nv_bfloat162*)&Cb[(size_t)r * ldc + c] = v0;
                *(__nv_bfloat162*)&Cb[(size_t)(r + 8) * ldc + c] = v1;
            } else {
                float b0 = bias ? bias[c] : 0.f;
                float b1 = bias ? bias[c + 1] : 0.f;
                float2 v0 = {d0 + b0, d1 + b1};
                float2 v1 = {d2 + b0, d3 + b1};
                *(float2*)&Cf[(size_t)r * ldc + c] = v0;
                *(float2*)&Cf[(size_t)(r + 8) * ldc + c] = v1;
            }
        }
    }
}

// ==================== head-shared local attention (fp32, sum-exp no-max) ====================
// block = RPB rows x ALL 8 heads; warp = head. K/V streamed once per block.
// dynamic smem: qs[RPB][QPITCH] | Kt[CTL][QPITCH] | Vt[CTL][QPITCH] | elists

#define LA3_QS   0
#define LA3_KT   (RPB * QPITCH)
#define LA3_VT   (LA3_KT + CTL * QPITCH)
#define LA3_FEND (LA3_VT + CTL * QPITCH)
#define LA3_SMEM (LA3_FEND * 4 + RPB * EMAX * 2 + RPB * EMAX + RPB * 4 + 128)

__global__ void __launch_bounds__(256) local_attn3(const float* __restrict__ eb,
                                                   const int* __restrict__ ei,
                                                   const int* __restrict__ et,
                                                   const int* __restrict__ cid) {
    extern __shared__ char dsm[];
    float* fs = (float*)dsm;
    float* qs = fs + LA3_QS;
    float* Kt = fs + LA3_KT;
    float* Vt = fs + LA3_VT;
    short* elj = (short*)(fs + LA3_FEND);
    unsigned char* elt = (unsigned char*)(elj + RPB * EMAX);
    int* ecnt = (int*)(elt + RPB * EMAX);

    int comm = blockIdx.y;
    int cs = g_cstart[comm];
    int L = g_cstart[comm + 1] - cs;
    if (L > MAXC) L = MAXC;
    int r0 = blockIdx.x * RPB;
    if (r0 >= L) return;

    int tid = threadIdx.x;
    int h = tid >> 5, lane = tid & 31;
    const float scale = 0.17677669529663687f;

    // load q rows (full 256 dims)
    for (int idx = tid; idx < RPB * DD; idx += 256) {
        int row = idx >> 8, d = idx & (DD - 1);
        int rr = r0 + row;
        int n = g_order[cs + ((rr < L) ? rr : 0)];
        qs[row * QPITCH + d] = g_qkv[n * QS_ + d];
    }
    // build per-row same-community edge lists (threads 0..RPB-1)
    if (tid < RPB) {
        int rr = r0 + tid;
        int cnt = 0;
        if (rr < L) {
            int n = g_order[cs + rr];
            for (int p = g_rowptr[n]; p < g_rowptr[n + 1]; p++) {
                int e = g_eidx[p];
                int dn = ei[EN + e];
                if (cid[dn] == comm && cnt < EMAX) {
                    int jj = g_inv[dn] - cs;
                    if (jj < L) {
                        elj[tid * EMAX + cnt] = (short)jj;
                        elt[tid * EMAX + cnt] = (unsigned char)et[e];
                        cnt++;
                    }
                }
            }
        }
        ecnt[tid] = cnt;
    }

    int row = lane >> 1;
    bool act = (r0 + row) < L;
    float qv[32];
    float o[32];
    float z = 0.f;
#pragma unroll
    for (int d = 0; d < 32; d++) o[d] = 0.f;
    __syncthreads();
#pragma unroll
    for (int d = 0; d < 32; d++) qv[d] = qs[row * QPITCH + h * 32 + d];

    for (int t0 = 0; t0 < L; t0 += CTL) {
        int tl = min(CTL, L - t0);
        __syncthreads();
        for (int idx = tid; idx < CTL * DD; idx += 256) {
            int c = idx >> 8, d = idx & (DD - 1);
            if (c < tl) {
                int m = g_order[cs + t0 + c];
                Kt[c * QPITCH + d] = g_qkv[m * QS_ + DD + d];
                Vt[c * QPITCH + d] = g_qkv[m * QS_ + 2 * DD + d];
            }
        }
        __syncthreads();
        if (act) {
            int cnt = ecnt[row];
            for (int cc = (lane & 1); cc < tl; cc += 2) {
                float s = 0.f;
#pragma unroll
                for (int d = 0; d < 32; d++) s += qv[d] * Kt[cc * QPITCH + h * 32 + d];
                s *= scale;
                int jg = t0 + cc;
                for (int p = 0; p < cnt; p++)
                    if (elj[row * EMAX + p] == jg)
                        s += eb[elt[row * EMAX + p] * HN + h];
                float pr = __expf(s);
                z += pr;
#pragma unroll
                for (int d = 0; d < 32; d++) o[d] += pr * Vt[cc * QPITCH + h * 32 + d];
            }
        }
    }

    // merge col-half partials (lane pairs)
#pragma unroll
    for (int d = 0; d < 32; d++) o[d] += __shfl_xor_sync(0xffffffffu, o[d], 1);
    z += __shfl_xor_sync(0xffffffffu, z, 1);

    if (act && (lane & 1) == 0) {
        int n = g_order[cs + r0 + row];
        float invz = 1.f / z;
#pragma unroll
        for (int d = 0; d < 32; d++) {
            float val = o[d] * invz;
            split1(val, g_xh[n * DD + h * 32 + d], g_xl[n * DD + h * 32 + d]);
        }
    }
}

// ==================== global masked softmax (bf16 in/out, in place) ====================
__global__ void softmax_glob_bf16(const int* __restrict__ cid) {
    __shared__ float red[256];
    int n = blockIdx.x, t = threadIdx.x;
    int c = cid[n];
    __nv_bfloat16* row = g_Sb + (size_t)n * NN_;

    float v[12];
    float mx = -1e30f;
#pragma unroll
    for (int i = 0; i < 12; i++) {
        int m = i * 256 + t;
        float x = (cid[m] != c) ? __bfloat162float(row[m]) : -1e30f;
        v[i] = x;
        mx = fmaxf(mx, x);
    }
    red[t] = mx;
    __syncthreads();
    for (int o = 128; o; o >>= 1) {
        if (t < o) red[t] = fmaxf(red[t], red[t + o]);
        __syncthreads();
    }
    float M0 = red[0];
    __syncthreads();
    float s = 0.f;
#pragma unroll
    for (int i = 0; i < 12; i++) {
        float p = (v[i] > -1e29f) ? __expf(v[i] - M0) : 0.f;
        v[i] = p;
        s += p;
    }
    red[t] = s;
    __syncthreads();
    for (int o = 128; o; o >>= 1) {
        if (t < o) red[t] += red[t + o];
        __syncthreads();
    }
    float inv = 1.f / red[0];
#pragma unroll
    for (int i = 0; i < 12; i++) {
        row[i * 256 + t] = __float2bfloat16(v[i] * inv);
    }
}

// ==================== host launcher ====================

extern "C" void kernel_launch(void* const* d_in, const int* in_sizes, int n_in,
                              void* d_out, int out_size) {
    const float* x   = (const float*)d_in[0];
    const int*   ei  = (const int*)d_in[1];
    const int*   et  = (const int*)d_in[2];
    const float* pos = (const float*)d_in[3];
    const int*   cid = (const int*)d_in[4];
    const float* emb_w = (const float*)d_in[6];
    const float* emb_b = (const float*)d_in[7];
    const float* loc_qw = (const float*)d_in[8];
    const float* loc_qb = (const float*)d_in[9];
    const float* loc_kw = (const float*)d_in[10];
    const float* loc_kb = (const float*)d_in[11];
    const float* loc_vw = (const float*)d_in[12];
    const float* loc_vb = (const float*)d_in[13];
    const float* loc_ow = (const float*)d_in[14];
    const float* loc_ob = (const float*)d_in[15];
    const float* loc_eb = (const float*)d_in[16];
    const float* loc_g  = (const float*)d_in[17];
    const float* loc_b  = (const float*)d_in[18];
    const float* glob_qw = (const float*)d_in[19];
    const float* glob_qb = (const float*)d_in[20];
    const float* glob_kw = (const float*)d_in[21];
    const float* glob_kb = (const float*)d_in[22];
    const float* glob_vw = (const float*)d_in[23];
    const float* glob_vb = (const float*)d_in[24];
    const float* glob_ow = (const float*)d_in[25];
    const float* glob_ob = (const float*)d_in[26];
    const float* glob_g  = (const float*)d_in[27];
    const float* glob_b  = (const float*)d_in[28];
    const float* out_w   = (const float*)d_in[29];
    const float* out_b   = (const float*)d_in[30];
    float* out = (float*)d_out;

    float *p_qkv, *p_slab, *p_bp;
    cudaGetSymbolAddress((void**)&p_qkv, g_qkv);
    cudaGetSymbolAddress((void**)&p_slab, g_slab);
    cudaGetSymbolAddress((void**)&p_bp, g_bpack);

    __nv_bfloat16 *p_xh, *p_xl, *p_qh, *p_kh, *p_vth, *p_Sb;
    __nv_bfloat16 *p_wqh, *p_wql, *p_owh, *p_owl, *p_outwh, *p_outwl;
    cudaGetSymbolAddress((void**)&p_xh, g_xh);
    cudaGetSymbolAddress((void**)&p_xl, g_xl);
    cudaGetSymbolAddress((void**)&p_qh, g_qh);
    cudaGetSymbolAddress((void**)&p_kh, g_kh);
    cudaGetSymbolAddress((void**)&p_vth, g_vth);
    cudaGetSymbolAddress((void**)&p_Sb, g_Sb);
    cudaGetSymbolAddress((void**)&p_wqh, g_wqh);
    cudaGetSymbolAddress((void**)&p_wql, g_wql);
    cudaGetSymbolAddress((void**)&p_owh, g_owh);
    cudaGetSymbolAddress((void**)&p_owl, g_owl);
    cudaGetSymbolAddress((void**)&p_outwh, g_outwh);
    cudaGetSymbolAddress((void**)&p_outwl, g_outwl);

    const int SM3 = STG3 * 2;
    const int SM1 = STG1 * 2;
    cudaFuncSetAttribute(mma_gemm_nt<3, false, false, false>, cudaFuncAttributeMaxDynamicSharedMemorySize, SM3);
    cudaFuncSetAttribute(mma_gemm_nt<3, false, false, true>,  cudaFuncAttributeMaxDynamicSharedMemorySize, SM3);
    cudaFuncSetAttribute(mma_gemm_nt<3, true, false, false>,  cudaFuncAttributeMaxDynamicSharedMemorySize, SM3);
    cudaFuncSetAttribute(mma_gemm_nt<1, true, false, false>,  cudaFuncAttributeMaxDynamicSharedMemorySize, SM1);
    cudaFuncSetAttribute(mma_gemm_nt<1, false, true, false>,  cudaFuncAttributeMaxDynamicSharedMemorySize, SM1);
    cudaFuncSetAttribute(local_attn3, cudaFuncAttributeMaxDynamicSharedMemorySize, LA3_SMEM);

    const float inv_sqrt_dh = 0.17677669529663687f;
    const __nv_bfloat16* nb = nullptr;
    const float* nf = nullptr;

    dim3 gQKV(12, 24, 1);      // 288 blocks
    dim3 gScore(48, 24, 1);    // 1152 blocks
    dim3 gPV(4, 24, 2);        // split-K=2 slabs, 192 blocks
    dim3 gProj(4, 24, 2);      // split-K=2 slabs, 192 blocks
    dim3 gOut(8, 24, 1);       // fused bias
    dim3 gLoc(MAXC / RPB, NCN, 1);

    // ---- setup (QKV layer 0 at launch index 3 = ncu capture slot) ----
    embed_split<<<NN_ * DD / 256, 256>>>(x, emb_w, emb_b, pos);                 // 0
    int pw_total = PW_R0 + PW_R1 + PW_R2 + PW_R3;
    prep_weights<<<(pw_total + 255) / 256, 256>>>(loc_qw, loc_kw, loc_vw,       // 1
                                                  glob_qw, glob_kw, glob_vw,
                                                  loc_ow, glob_ow, out_w,
                                                  loc_qb, loc_kb, loc_vb,
                                                  glob_qb, glob_kb, glob_vb);
    build_perm2<<<1, 1024>>>(cid);                                              // 2
    mma_gemm_nt<3, false, false, false><<<gQKV, 256, SM3>>>(                    // 3 (profiled)
        p_xh, p_xl, DD, p_wqh, p_wql, DD,
        p_bp, p_qkv, QS_, DD, 1.f, DD, 0);
    count_deg<<<EN / 256, 256>>>(ei);                                           // 4
    scan_deg<<<1, 1024>>>();                                                    // 5
    scatter_edges<<<EN / 256, 256>>>(ei);                                       // 6

    // ---- local layers ----
    for (int l = 0; l < 2; l++) {
        if (l == 1) {
            mma_gemm_nt<3, false, false, false><<<gQKV, 256, SM3>>>(
                p_xh, p_xl, DD, p_wqh + l * QS_ * DD, p_wql + l * QS_ * DD, DD,
                p_bp + l * QS_, p_qkv, QS_, DD, 1.f, DD, 0);
        }
        local_attn3<<<gLoc, 256, LA3_SMEM>>>(loc_eb + l * NETN * HN, ei, et, cid);
        mma_gemm_nt<3, true, false, false><<<gProj, 256, SM3>>>(
            p_xh, p_xl, DD, p_owh + l * DD * DD, p_owl + l * DD * DD, DD,
            nf, p_slab, DD, DD, 1.f, 128, (size_t)NN_ * DD);
        ln_res_f<<<NN_ / 8, 256>>>(loc_g + l * DD, loc_b + l * DD,
                                   (l == 0) ? pos : nf,
                                   loc_ob + l * DD);
    }

    // ---- global layers ----
    for (int g = 0; g < 2; g++) {
        mma_gemm_nt<3, false, false, true><<<gQKV, 256, SM3>>>(
            p_xh, p_xl, DD, p_wqh + (2 + g) * QS_ * DD, p_wql + (2 + g) * QS_ * DD, DD,
            p_bp + (2 + g) * QS_, nullptr, 0, DD, 1.f, DD, 0);
        mma_gemm_nt<1, false, true, false><<<gScore, 256, SM1>>>(
            p_qh, nb, DD, p_kh, nb, DD,
            nf, p_Sb, NN_, DD, inv_sqrt_dh, DD, 0);
        softmax_glob_bf16<<<NN_, 256>>>(cid);
        mma_gemm_nt<1, true, false, false><<<gPV, 256, SM1>>>(
            p_Sb, nb, NN_, p_vth, nb, NN_,
            nf, p_slab, DD, NN_, 1.f, NN_ / 2, (size_t)NN_ * DD);
        reduce_pv_split<<<NN_ * DD / 256, 256>>>();
        mma_gemm_nt<3, true, false, false><<<gProj, 256, SM3>>>(
            p_xh, p_xl, DD, p_owh + (2 + g) * DD * DD, p_owl + (2 + g) * DD * DD, DD,
            nf, p_slab, DD, DD, 1.f, 128, (size_t)NN_ * DD);
        ln_res_f<<<NN_ / 8, 256>>>(glob_g + g * DD, glob_b + g * DD,
                                   nf, glob_ob + g * DD);
    }

    // ---- output projection (3-pass, fused bias) ----
    mma_gemm_nt<3, false, false, false><<<gOut, 256, SM3>>>(
        p_xh, p_xl, DD, p_outwh, p_outwl, DD,
        out_b, out, OD, DD, 1.f, DD, 0);
}

// round 15
// speedup vs baseline: 1.3199x; 1.3199x over previous
#include <cuda_runtime.h>
#include <cuda_bf16.h>
#include <cstdint>
#include <math.h>

// Problem constants
#define NN_   3072      // nodes
#define DD    256       // hidden dim
#define OD    512       // output dim
#define HN    8         // heads
#define DHD   32        // head dim
#define EN    49152     // edges
#define NETN  5         // edge types
#define NCN   8         // communities
#define MAXC  640       // max community size (actual ~384)
#define QS_   (3 * DD)

// ---------------- device scratch (static; no allocation) ----------------
__device__ __align__(16) float g_h[NN_ * DD];
__device__ __align__(16) float g_qkv[NN_ * QS_];          // fused Q|K|V fp32 (local layers)
__device__ __align__(16) float g_slab[2 * NN_ * QS_];     // split-K partial outputs
__device__ __align__(16) float g_bpack[4 * QS_];          // packed QKV biases

__device__ __align__(16) __nv_bfloat16 g_xh[NN_ * DD],  g_xl[NN_ * DD];
__device__ __align__(16) __nv_bfloat16 g_qh[NN_ * DD];
__device__ __align__(16) __nv_bfloat16 g_kh[NN_ * DD];
__device__ __align__(16) __nv_bfloat16 g_vth[DD * NN_];                    // V^T
__device__ __align__(16) __nv_bfloat16 g_Sb[(size_t)NN_ * NN_];            // S -> P in place
__device__ __align__(16) __nv_bfloat16 g_wqh[4 * QS_ * DD], g_wql[4 * QS_ * DD];
__device__ __align__(16) __nv_bfloat16 g_owh[4 * DD * DD],  g_owl[4 * DD * DD];
__device__ __align__(16) __nv_bfloat16 g_outwh[OD * DD],    g_outwl[OD * DD];

__device__ int g_order[NN_];
__device__ int g_inv[NN_];
__device__ int g_cstart[NCN + 1];
__device__ int g_deg[NN_];
__device__ int g_rowptr[NN_ + 1];
__device__ int g_cur[NN_];
__device__ int g_eidx[EN];

// ==================== small helpers ====================

__device__ __forceinline__ uint32_t smem_u32(const void* p) {
    uint32_t a;
    asm("{ .reg .u64 t; cvta.to.shared.u64 t, %1; cvt.u32.u64 %0, t; }" : "=r"(a) : "l"(p));
    return a;
}

__device__ __forceinline__ void cpa16(uint32_t s, const void* g) {
    asm volatile("cp.async.cg.shared.global [%0], [%1], 16;\n" :: "r"(s), "l"(g) : "memory");
}

__device__ __forceinline__ void split1(float x, __nv_bfloat16& h, __nv_bfloat16& l) {
    h = __float2bfloat16(x);
    l = __float2bfloat16(x - __bfloat162float(h));
}

__device__ __forceinline__ void ldsm_x4(uint32_t* r, uint32_t addr) {
    asm volatile("ldmatrix.sync.aligned.m8n8.x4.shared.b16 {%0,%1,%2,%3}, [%4];"
        : "=r"(r[0]), "=r"(r[1]), "=r"(r[2]), "=r"(r[3]) : "r"(addr));
}

// ==================== setup kernels ====================

// also zeroes g_deg
__global__ void build_perm2(const int* __restrict__ cid) {
    __shared__ int cnt[NCN][1024];
    int t = threadIdx.x;
    for (int i = t; i < NN_; i += 1024) g_deg[i] = 0;
    int base = t * 3;
    int c0 = cid[base], c1 = cid[base + 1], c2 = cid[base + 2];
    int loc[NCN];
#pragma unroll
    for (int c = 0; c < NCN; c++) loc[c] = 0;
    loc[c0]++; loc[c1]++; loc[c2]++;
#pragma unroll
    for (int c = 0; c < NCN; c++) cnt[c][t] = loc[c];
    __syncthreads();
    for (int off = 1; off < 1024; off <<= 1) {
        int v[NCN];
#pragma unroll
        for (int c = 0; c < NCN; c++) v[c] = (t >= off) ? cnt[c][t - off] : 0;
        __syncthreads();
#pragma unroll
        for (int c = 0; c < NCN; c++) cnt[c][t] += v[c];
        __syncthreads();
    }
    if (t == 0) {
        int a = 0;
        for (int c = 0; c < NCN; c++) { g_cstart[c] = a; a += cnt[c][1023]; }
        g_cstart[NCN] = a;
    }
    __syncthreads();
    int excl[NCN];
#pragma unroll
    for (int c = 0; c < NCN; c++) excl[c] = (t > 0) ? cnt[c][t - 1] : 0;
#pragma unroll
    for (int i = 0; i < 3; i++) {
        int n = base + i;
        int c = cid[n];
        int p = g_cstart[c] + excl[c];
        excl[c]++;
        g_order[p] = n;
        g_inv[n] = p;
    }
}

__global__ void count_deg(const int* __restrict__ ei) {
    int e = blockIdx.x * 256 + threadIdx.x;
    if (e < EN) atomicAdd(&g_deg[ei[e]], 1);
}

__global__ void scan_deg() {
    __shared__ int s[1024];
    int t = threadIdx.x;
    int b = t * 3;
    int d0 = g_deg[b], d1 = g_deg[b + 1], d2 = g_deg[b + 2];
    s[t] = d0 + d1 + d2;
    __syncthreads();
    for (int off = 1; off < 1024; off <<= 1) {
        int v = (t >= off) ? s[t - off] : 0;
        __syncthreads();
        s[t] += v;
        __syncthreads();
    }
    int excl = (t > 0) ? s[t - 1] : 0;
    g_rowptr[b] = excl;       g_cur[b]     = excl;
    g_rowptr[b + 1] = excl + d0; g_cur[b + 1] = excl + d0;
    g_rowptr[b + 2] = excl + d0 + d1; g_cur[b + 2] = excl + d0 + d1;
    if (t == 1023) g_rowptr[NN_] = s[1023];
}

__global__ void scatter_edges(const int* __restrict__ ei) {
    int e = blockIdx.x * 256 + threadIdx.x;
    if (e >= EN) return;
    int s = ei[e];
    int p = atomicAdd(&g_cur[s], 1);
    g_eidx[p] = e;
}

// fused weight prep
#define PW_R0 (4 * QS_ * DD)
#define PW_R1 (4 * DD * DD)
#define PW_R2 (OD * DD)
#define PW_R3 (4 * QS_)
__global__ void prep_weights(
    const float* __restrict__ lqw, const float* __restrict__ lkw, const float* __restrict__ lvw,
    const float* __restrict__ gqw, const float* __restrict__ gkw, const float* __restrict__ gvw,
    const float* __restrict__ low, const float* __restrict__ gow, const float* __restrict__ outw,
    const float* __restrict__ lqb, const float* __restrict__ lkb, const float* __restrict__ lvb,
    const float* __restrict__ gqb, const float* __restrict__ gkb, const float* __restrict__ gvb)
{
    int i = blockIdx.x * 256 + threadIdx.x;
    if (i < PW_R0) {
        int l = i / (QS_ * DD);
        int rem = i - l * (QS_ * DD);
        int n = rem / DD;
        int k = rem - n * DD;
        int sel = n >> 8;
        int nn = n & (DD - 1);
        const float* qw = (l < 2) ? lqw : gqw;
        const float* kw = (l < 2) ? lkw : gkw;
        const float* vw = (l < 2) ? lvw : gvw;
        int loff = ((l < 2) ? l : (l - 2)) * DD * DD;
        const float* src = (sel == 0) ? qw : (sel == 1) ? kw : vw;
        split1(src[loff + k * DD + nn], g_wqh[i], g_wql[i]);
        return;
    }
    i -= PW_R0;
    if (i < PW_R1) {
        int l = i / (DD * DD);
        int rem = i - l * (DD * DD);
        int n = rem / DD, k = rem - n * DD;
        const float* src = (l < 2) ? low : gow;
        int loff = ((l < 2) ? l : (l - 2)) * DD * DD;
        split1(src[loff + k * DD + n], g_owh[l * DD * DD + rem], g_owl[l * DD * DD + rem]);
        return;
    }
    i -= PW_R1;
    if (i < PW_R2) {
        int n = i / DD, k = i - n * DD;
        split1(outw[k * OD + n], g_outwh[i], g_outwl[i]);
        return;
    }
    i -= PW_R2;
    if (i < PW_R3) {
        int l = i / QS_;
        int n = i - l * QS_;
        int sel = n >> 8;
        int nn = n & (DD - 1);
        const float* qb = (l < 2) ? lqb : gqb;
        const float* kb = (l < 2) ? lkb : gkb;
        const float* vb = (l < 2) ? lvb : gvb;
        int loff = ((l < 2) ? l : (l - 2)) * DD;
        const float* src = (sel == 0) ? qb : (sel == 1) ? kb : vb;
        g_bpack[i] = src[loff + nn];
    }
}

// ==================== fused elementwise kernels ====================

__global__ void embed_split(const float* __restrict__ x, const float* __restrict__ w,
                            const float* __restrict__ b, const float* __restrict__ pos) {
    int i = blockIdx.x * 256 + threadIdx.x;
    int d = i & (DD - 1);
    float hh = x[i >> 8] * w[d] + b[d];
    g_h[i] = hh;
    split1(hh + pos[i], g_xh[i], g_xl[i]);
}

// xh/xl = split(sum of 2 PV slabs)
__global__ void reduce_pv_split() {
    int i = blockIdx.x * 256 + threadIdx.x;
    float s = g_slab[i] + g_slab[NN_ * DD + i];
    split1(s, g_xh[i], g_xl[i]);
}

// h = LayerNorm(h + sum2slabs + bias)*g + b ; xh/xl = split(h [+ pos])
__global__ void ln_res_f(const float* __restrict__ gam, const float* __restrict__ bet,
                         const float* __restrict__ pos, const float* __restrict__ bias) {
    int w = threadIdx.x >> 5, lane = threadIdx.x & 31;
    int n = blockIdx.x * 8 + w;
    const int base = n * DD;
    float v[8];
    float s = 0.f;
#pragma unroll
    for (int i = 0; i < 8; i++) {
        int d = i * 32 + lane;
        int idx = base + d;
        float t = g_slab[idx] + g_slab[NN_ * DD + idx] + bias[d];
        v[i] = g_h[idx] + t;
        s += v[i];
    }
#pragma unroll
    for (int o = 16; o; o >>= 1) s += __shfl_xor_sync(0xffffffffu, s, o);
    float mean = s * (1.f / DD);
    float vs = 0.f;
#pragma unroll
    for (int i = 0; i < 8; i++) { float d = v[i] - mean; vs += d * d; }
#pragma unroll
    for (int o = 16; o; o >>= 1) vs += __shfl_xor_sync(0xffffffffu, vs, o);
    float r = rsqrtf(vs * (1.f / DD) + 1e-5f);
#pragma unroll
    for (int i = 0; i < 8; i++) {
        int d = i * 32 + lane;
        float y = (v[i] - mean) * r * gam[d] + bet[d];
        g_h[base + d] = y;
        float z = pos ? (y + pos[base + d]) : y;
        split1(z, g_xh[base + d], g_xl[base + d]);
    }
}

// ==================== mma.sync GEMM: 128x64 tile ====================

#define KCH  32
#define SSTR 40
#define TILEA (128 * SSTR * 2)
#define TILEB64 (64 * SSTR * 2)
#define STG3 (2 * TILEA + 2 * TILEB64)
#define STG1 (TILEA + TILEB64)

__device__ __forceinline__ void mma16816(float* d, const uint32_t* a, const uint32_t* b) {
    asm volatile(
        "mma.sync.aligned.m16n8k16.row.col.f32.bf16.bf16.f32 "
        "{%0,%1,%2,%3}, {%4,%5,%6,%7}, {%8,%9}, {%0,%1,%2,%3};\n"
        : "+f"(d[0]), "+f"(d[1]), "+f"(d[2]), "+f"(d[3])
        : "r"(a[0]), "r"(a[1]), "r"(a[2]), "r"(a[3]), "r"(b[0]), "r"(b[1]));
}

template<int PASSES, bool SLAB, bool BF16OUT, bool QKVB>
__global__ void __launch_bounds__(256, 2) mma_gemm_nt(
    const __nv_bfloat16* __restrict__ Ah, const __nv_bfloat16* __restrict__ Al, int lda,
    const __nv_bfloat16* __restrict__ Bh, const __nv_bfloat16* __restrict__ Bl, int ldb,
    const float* __restrict__ bias, void* __restrict__ Cv, int ldc,
    int K, float alpha, int kchunk, size_t slabstride)
{
    extern __shared__ char dsm[];
    const int STAGE = (PASSES == 3) ? STG3 : STG1;
    const uint32_t OFF_BH = (PASSES == 3) ? 2 * TILEA : TILEA;
    const uint32_t sbase = smem_u32(dsm);

    const int tid = threadIdx.x;
    const int lane = tid & 31;
    const int wid = tid >> 5;
    const int warp_m = wid & 3;
    const int warp_n = wid >> 2;
    const int bm = blockIdx.y * 128, bn = blockIdx.x * 64;
    const int kbeg = blockIdx.z * kchunk;
    int kend = kbeg + kchunk;
    if (kend > K) kend = K;
    const int nch = (kend - kbeg) / KCH;

    const int r0 = tid >> 2;
    const int c4 = tid & 3;
    const uint32_t soA0 = (uint32_t)(r0 * SSTR + c4 * 8) * 2;
    const uint32_t soA1 = (uint32_t)((r0 + 64) * SSTR + c4 * 8) * 2;
    const uint32_t soB  = soA0;

    const uint32_t lane7 = lane & 7;
    const uint32_t aoff0 = (uint32_t)((warp_m * 32 + ((lane >> 3) & 1) * 8 + lane7) * SSTR) * 2
                         + (uint32_t)(lane >> 4) * 16;
    const uint32_t aoff1 = aoff0 + (uint32_t)(16 * SSTR) * 2;
    uint32_t boff[2];
#pragma unroll
    for (int jj = 0; jj < 2; jj++)
        boff[jj] = (uint32_t)((warp_n * 32 + jj * 16 + (lane >> 4) * 8 + lane7) * SSTR) * 2
                 + (uint32_t)((lane >> 3) & 1) * 16;

    auto issue = [&](int ch) {
        int k0 = kbeg + ch * KCH;
        uint32_t st = sbase + (uint32_t)(ch & 1) * STAGE;
        const __nv_bfloat16* a0 = Ah + (size_t)(bm + r0) * lda + k0 + c4 * 8;
        const __nv_bfloat16* b0 = Bh + (size_t)(bn + r0) * ldb + k0 + c4 * 8;
        cpa16(st + soA0, a0);
        cpa16(st + soA1, a0 + (size_t)64 * lda);
        cpa16(st + OFF_BH + soB, b0);
        if (PASSES == 3) {
            const __nv_bfloat16* a1 = Al + (size_t)(bm + r0) * lda + k0 + c4 * 8;
            const __nv_bfloat16* b1 = Bl + (size_t)(bn + r0) * ldb + k0 + c4 * 8;
            cpa16(st + TILEA + soA0, a1);
            cpa16(st + TILEA + soA1, a1 + (size_t)64 * lda);
            cpa16(st + OFF_BH + TILEB64 + soB, b1);
        }
        asm volatile("cp.async.commit_group;\n" ::: "memory");
    };

    float acc[2][4][4];
#pragma unroll
    for (int i = 0; i < 2; i++)
#pragma unroll
        for (int j = 0; j < 4; j++)
#pragma unroll
            for (int q = 0; q < 4; q++) acc[i][j][q] = 0.f;

    issue(0);
    for (int ch = 0; ch < nch; ch++) {
        if (ch + 1 < nch) {
            issue(ch + 1);
            asm volatile("cp.async.wait_group 1;\n" ::: "memory");
        } else {
            asm volatile("cp.async.wait_group 0;\n" ::: "memory");
        }
        __syncthreads();

        const uint32_t stage = sbase + (uint32_t)(ch & 1) * STAGE;

#pragma unroll
        for (int ks = 0; ks < 2; ks++) {
            const uint32_t kso = (uint32_t)ks * 32;
            uint32_t a0[4], a1[4], bh[2][4];
            ldsm_x4(a0, stage + aoff0 + kso);
            ldsm_x4(a1, stage + aoff1 + kso);
            ldsm_x4(bh[0], stage + OFF_BH + boff[0] + kso);
            ldsm_x4(bh[1], stage + OFF_BH + boff[1] + kso);
#pragma unroll
            for (int jj = 0; jj < 2; jj++) {
                mma16816(acc[0][2 * jj],     a0, bh[jj]);
                mma16816(acc[1][2 * jj],     a1, bh[jj]);
                mma16816(acc[0][2 * jj + 1], a0, bh[jj] + 2);
                mma16816(acc[1][2 * jj + 1], a1, bh[jj] + 2);
            }
            if (PASSES == 3) {
                uint32_t bl[2][4];
                ldsm_x4(bl[0], stage + OFF_BH + TILEB64 + boff[0] + kso);
                ldsm_x4(bl[1], stage + OFF_BH + TILEB64 + boff[1] + kso);
#pragma unroll
                for (int jj = 0; jj < 2; jj++) {
                    mma16816(acc[0][2 * jj],     a0, bl[jj]);
                    mma16816(acc[1][2 * jj],     a1, bl[jj]);
                    mma16816(acc[0][2 * jj + 1], a0, bl[jj] + 2);
                    mma16816(acc[1][2 * jj + 1], a1, bl[jj] + 2);
                }
                uint32_t al0[4], al1[4];
                ldsm_x4(al0, stage + TILEA + aoff0 + kso);
                ldsm_x4(al1, stage + TILEA + aoff1 + kso);
#pragma unroll
                for (int jj = 0; jj < 2; jj++) {
                    mma16816(acc[0][2 * jj],     al0, bh[jj]);
                    mma16816(acc[1][2 * jj],     al1, bh[jj]);
                    mma16816(acc[0][2 * jj + 1], al0, bh[jj] + 2);
                    mma16816(acc[1][2 * jj + 1], al1, bh[jj] + 2);
                }
            }
        }
        __syncthreads();
    }

    float* Cf = (float*)Cv;
    __nv_bfloat16* Cb = (__nv_bfloat16*)Cv;
    if (SLAB) Cf += (size_t)blockIdx.z * slabstride;
    const int row = bm + warp_m * 32 + (lane >> 2);
    const int col = bn + warp_n * 32 + (lane & 3) * 2;
#pragma unroll
    for (int i = 0; i < 2; i++) {
#pragma unroll
        for (int j = 0; j < 4; j++) {
            int r = row + i * 16;
            int c = col + j * 8;
            float d0 = alpha * acc[i][j][0];
            float d1 = alpha * acc[i][j][1];
            float d2 = alpha * acc[i][j][2];
            float d3 = alpha * acc[i][j][3];
            if (QKVB) {
                float b0 = bias[c], b1 = bias[c + 1];
                d0 += b0; d1 += b1; d2 += b0; d3 += b1;
                __nv_bfloat16 v00 = __float2bfloat16(d0);
                __nv_bfloat16 v01 = __float2bfloat16(d1);
                __nv_bfloat16 v10 = __float2bfloat16(d2);
                __nv_bfloat16 v11 = __float2bfloat16(d3);
                int sel = c >> 8;
                int cc = c & (DD - 1);
                if (sel == 0) {
                    *(__nv_bfloat162*)&g_qh[r * DD + cc] = {v00, v01};
                    *(__nv_bfloat162*)&g_qh[(r + 8) * DD + cc] = {v10, v11};
                } else if (sel == 1) {
                    *(__nv_bfloat162*)&g_kh[r * DD + cc] = {v00, v01};
                    *(__nv_bfloat162*)&g_kh[(r + 8) * DD + cc] = {v10, v11};
                } else {
                    g_vth[(size_t)cc * NN_ + r] = v00;
                    g_vth[(size_t)(cc + 1) * NN_ + r] = v01;
                    g_vth[(size_t)cc * NN_ + r + 8] = v10;
                    g_vth[(size_t)(cc + 1) * NN_ + r + 8] = v11;
                }
            } else if (BF16OUT) {
                __nv_bfloat162 v0, v1;
                v0.x = __float2bfloat16(d0); v0.y = __float2bfloat16(d1);
                v1.x = __float2bfloat16(d2); v1.y = __float2bfloat16(d3);
                *(__nv_bfloat162*)&Cb[(size_t)r * ldc + c] = v0;
                *(__nv_bfloat162*)&Cb[(size_t)(r + 8) * ldc + c] = v1;
            } else {
                float b0 = bias ? bias[c] : 0.f;
                float b1 = bias ? bias[c + 1] : 0.f;
                float2 v0 = {d0 + b0, d1 + b1};
                float2 v1 = {d2 + b0, d3 + b1};
                *(float2*)&Cf[(size_t)r * ldc + c] = v0;
                *(float2*)&Cf[(size_t)(r + 8) * ldc + c] = v1;
            }
        }
    }
}

// ==================== community-chunked local attention (R13-proven) ====================
#define KTC 128

__global__ void __launch_bounds__(256) local_attn2(const float* __restrict__ eb,
                                                   const int* __restrict__ ei,
                                                   const int* __restrict__ et,
                                                   const int* __restrict__ cid) {
    __shared__ float sc[8][MAXC];
    __shared__ float Kt[32][KTC + 1];
    __shared__ float sq[8][32];

    int chunk = blockIdx.x, comm = blockIdx.y, h = blockIdx.z;
    int cs = g_cstart[comm];
    int L = g_cstart[comm + 1] - cs;
    if (L > MAXC) L = MAXC;
    if (chunk * 8 >= L) return;

    int tid = threadIdx.x;
    int w = tid >> 5, lane = tid & 31;
    int r = chunk * 8 + w;
    bool act = r < L;
    int n = g_order[cs + (act ? r : 0)];
    const float scale = 0.17677669529663687f;

    sq[w][lane] = g_qkv[n * QS_ + h * 32 + lane];
    __syncwarp();
    float qv[32];
#pragma unroll
    for (int d = 0; d < 32; d++) qv[d] = sq[w][d];

    // ---- scores ----
    for (int t0 = 0; t0 < L; t0 += KTC) {
        int tl = min(KTC, L - t0);
        __syncthreads();
        for (int j = w; j < tl; j += 8) {
            int m = g_order[cs + t0 + j];
            Kt[lane][j] = g_qkv[m * QS_ + DD + h * 32 + lane];
        }
        __syncthreads();
        if (act) {
            for (int j0 = 0; j0 < tl; j0 += 32) {
                int j = j0 + lane;
                int jc = (j < tl) ? j : (tl - 1);
                float s = 0.f;
#pragma unroll
                for (int d = 0; d < 32; d++) s += qv[d] * Kt[d][jc];
                if (j < tl) sc[w][t0 + j] = s * scale;
            }
        }
    }

    // ---- edge-type bias ----
    float invs = 1.f;
    if (act) {
        __syncwarp();
        int e0 = g_rowptr[n], e1 = g_rowptr[n + 1];
        for (int p = e0 + lane; p < e1; p += 32) {
            int e = g_eidx[p];
            int dn = ei[EN + e];
            if (cid[dn] == comm) {
                int jj = g_inv[dn] - cs;
                if (jj < L) atomicAdd(&sc[w][jj], eb[et[e] * HN + h]);
            }
        }
        __syncwarp();

        float mx = -1e30f;
        for (int j = lane; j < L; j += 32) mx = fmaxf(mx, sc[w][j]);
#pragma unroll
        for (int o = 16; o; o >>= 1) mx = fmaxf(mx, __shfl_xor_sync(0xffffffffu, mx, o));
        float sum = 0.f;
        for (int j = lane; j < L; j += 32) {
            float p = __expf(sc[w][j] - mx);
            sc[w][j] = p;
            sum += p;
        }
#pragma unroll
        for (int o = 16; o; o >>= 1) sum += __shfl_xor_sync(0xffffffffu, sum, o);
        invs = 1.f / sum;
        __syncwarp();
    }

    // ---- PV ----
    float o = 0.f;
    for (int t0 = 0; t0 < L; t0 += KTC) {
        int tl = min(KTC, L - t0);
        __syncthreads();
        for (int j = w; j < tl; j += 8) {
            int m = g_order[cs + t0 + j];
            Kt[lane][j] = g_qkv[m * QS_ + 2 * DD + h * 32 + lane];
        }
        __syncthreads();
        if (act) {
            int j = 0;
            for (; j + 3 < tl; j += 4) {
                o += sc[w][t0 + j]     * Kt[lane][j];
                o += sc[w][t0 + j + 1] * Kt[lane][j + 1];
                o += sc[w][t0 + j + 2] * Kt[lane][j + 2];
                o += sc[w][t0 + j + 3] * Kt[lane][j + 3];
            }
            for (; j < tl; j++) o += sc[w][t0 + j] * Kt[lane][j];
        }
    }
    if (act) {
        float ov = o * invs;
        split1(ov, g_xh[n * DD + h * 32 + lane], g_xl[n * DD + h * 32 + lane]);
    }
}

// ==================== global masked softmax (bf16 in/out, in place) ====================
__global__ void softmax_glob_bf16(const int* __restrict__ cid) {
    __shared__ float red[256];
    int n = blockIdx.x, t = threadIdx.x;
    int c = cid[n];
    __nv_bfloat16* row = g_Sb + (size_t)n * NN_;

    float v[12];
    float mx = -1e30f;
#pragma unroll
    for (int i = 0; i < 12; i++) {
        int m = i * 256 + t;
        float x = (cid[m] != c) ? __bfloat162float(row[m]) : -1e30f;
        v[i] = x;
        mx = fmaxf(mx, x);
    }
    red[t] = mx;
    __syncthreads();
    for (int o = 128; o; o >>= 1) {
        if (t < o) red[t] = fmaxf(red[t], red[t + o]);
        __syncthreads();
    }
    float M0 = red[0];
    __syncthreads();
    float s = 0.f;
#pragma unroll
    for (int i = 0; i < 12; i++) {
        float p = (v[i] > -1e29f) ? __expf(v[i] - M0) : 0.f;
        v[i] = p;
        s += p;
    }
    red[t] = s;
    __syncthreads();
    for (int o = 128; o; o >>= 1) {
        if (t < o) red[t] += red[t + o];
        __syncthreads();
    }
    float inv = 1.f / red[0];
#pragma unroll
    for (int i = 0; i < 12; i++) {
        row[i * 256 + t] = __float2bfloat16(v[i] * inv);
    }
}

// ==================== host launcher ====================

extern "C" void kernel_launch(void* const* d_in, const int* in_sizes, int n_in,
                              void* d_out, int out_size) {
    const float* x   = (const float*)d_in[0];
    const int*   ei  = (const int*)d_in[1];
    const int*   et  = (const int*)d_in[2];
    const float* pos = (const float*)d_in[3];
    const int*   cid = (const int*)d_in[4];
    const float* emb_w = (const float*)d_in[6];
    const float* emb_b = (const float*)d_in[7];
    const float* loc_qw = (const float*)d_in[8];
    const float* loc_qb = (const float*)d_in[9];
    const float* loc_kw = (const float*)d_in[10];
    const float* loc_kb = (const float*)d_in[11];
    const float* loc_vw = (const float*)d_in[12];
    const float* loc_vb = (const float*)d_in[13];
    const float* loc_ow = (const float*)d_in[14];
    const float* loc_ob = (const float*)d_in[15];
    const float* loc_eb = (const float*)d_in[16];
    const float* loc_g  = (const float*)d_in[17];
    const float* loc_b  = (const float*)d_in[18];
    const float* glob_qw = (const float*)d_in[19];
    const float* glob_qb = (const float*)d_in[20];
    const float* glob_kw = (const float*)d_in[21];
    const float* glob_kb = (const float*)d_in[22];
    const float* glob_vw = (const float*)d_in[23];
    const float* glob_vb = (const float*)d_in[24];
    const float* glob_ow = (const float*)d_in[25];
    const float* glob_ob = (const float*)d_in[26];
    const float* glob_g  = (const float*)d_in[27];
    const float* glob_b  = (const float*)d_in[28];
    const float* out_w   = (const float*)d_in[29];
    const float* out_b   = (const float*)d_in[30];
    float* out = (float*)d_out;

    float *p_qkv, *p_slab, *p_bp;
    cudaGetSymbolAddress((void**)&p_qkv, g_qkv);
    cudaGetSymbolAddress((void**)&p_slab, g_slab);
    cudaGetSymbolAddress((void**)&p_bp, g_bpack);

    __nv_bfloat16 *p_xh, *p_xl, *p_qh, *p_kh, *p_vth, *p_Sb;
    __nv_bfloat16 *p_wqh, *p_wql, *p_owh, *p_owl, *p_outwh, *p_outwl;
    cudaGetSymbolAddress((void**)&p_xh, g_xh);
    cudaGetSymbolAddress((void**)&p_xl, g_xl);
    cudaGetSymbolAddress((void**)&p_qh, g_qh);
    cudaGetSymbolAddress((void**)&p_kh, g_kh);
    cudaGetSymbolAddress((void**)&p_vth, g_vth);
    cudaGetSymbolAddress((void**)&p_Sb, g_Sb);
    cudaGetSymbolAddress((void**)&p_wqh, g_wqh);
    cudaGetSymbolAddress((void**)&p_wql, g_wql);
    cudaGetSymbolAddress((void**)&p_owh, g_owh);
    cudaGetSymbolAddress((void**)&p_owl, g_owl);
    cudaGetSymbolAddress((void**)&p_outwh, g_outwh);
    cudaGetSymbolAddress((void**)&p_outwl, g_outwl);

    const int SM3 = STG3 * 2;
    const int SM1 = STG1 * 2;
    cudaFuncSetAttribute(mma_gemm_nt<3, false, false, false>, cudaFuncAttributeMaxDynamicSharedMemorySize, SM3);
    cudaFuncSetAttribute(mma_gemm_nt<3, false, false, true>,  cudaFuncAttributeMaxDynamicSharedMemorySize, SM3);
    cudaFuncSetAttribute(mma_gemm_nt<3, true, false, false>,  cudaFuncAttributeMaxDynamicSharedMemorySize, SM3);
    cudaFuncSetAttribute(mma_gemm_nt<1, true, false, false>,  cudaFuncAttributeMaxDynamicSharedMemorySize, SM1);
    cudaFuncSetAttribute(mma_gemm_nt<1, false, true, false>,  cudaFuncAttributeMaxDynamicSharedMemorySize, SM1);

    const float inv_sqrt_dh = 0.17677669529663687f;
    const __nv_bfloat16* nb = nullptr;
    const float* nf = nullptr;

    dim3 gQKV(12, 24, 1);      // 288 blocks
    dim3 gScore(48, 24, 1);    // 1152 blocks
    dim3 gPV(4, 24, 2);        // split-K=2 slabs, 192 blocks
    dim3 gProj(4, 24, 2);      // split-K=2 slabs, 192 blocks
    dim3 gOut(8, 24, 1);       // fused bias
    dim3 gLoc(MAXC / 8, NCN, HN);

    // ---- setup (QKV layer 0 at launch index 3 = ncu capture slot) ----
    embed_split<<<NN_ * DD / 256, 256>>>(x, emb_w, emb_b, pos);                 // 0
    int pw_total = PW_R0 + PW_R1 + PW_R2 + PW_R3;
    prep_weights<<<(pw_total + 255) / 256, 256>>>(loc_qw, loc_kw, loc_vw,       // 1
                                                  glob_qw, glob_kw, glob_vw,
                                                  loc_ow, glob_ow, out_w,
                                                  loc_qb, loc_kb, loc_vb,
                                                  glob_qb, glob_kb, glob_vb);
    build_perm2<<<1, 1024>>>(cid);                                              // 2
    mma_gemm_nt<3, false, false, false><<<gQKV, 256, SM3>>>(                    // 3 (profiled)
        p_xh, p_xl, DD, p_wqh, p_wql, DD,
        p_bp, p_qkv, QS_, DD, 1.f, DD, 0);
    count_deg<<<EN / 256, 256>>>(ei);                                           // 4
    scan_deg<<<1, 1024>>>();                                                    // 5
    scatter_edges<<<EN / 256, 256>>>(ei);                                       // 6

    // ---- local layers ----
    for (int l = 0; l < 2; l++) {
        if (l == 1) {
            mma_gemm_nt<3, false, false, false><<<gQKV, 256, SM3>>>(
                p_xh, p_xl, DD, p_wqh + l * QS_ * DD, p_wql + l * QS_ * DD, DD,
                p_bp + l * QS_, p_qkv, QS_, DD, 1.f, DD, 0);
        }
        local_attn2<<<gLoc, 256>>>(loc_eb + l * NETN * HN, ei, et, cid);
        mma_gemm_nt<3, true, false, false><<<gProj, 256, SM3>>>(
            p_xh, p_xl, DD, p_owh + l * DD * DD, p_owl + l * DD * DD, DD,
            nf, p_slab, DD, DD, 1.f, 128, (size_t)NN_ * DD);
        ln_res_f<<<NN_ / 8, 256>>>(loc_g + l * DD, loc_b + l * DD,
                                   (l == 0) ? pos : nf,
                                   loc_ob + l * DD);
    }

    // ---- global layers ----
    for (int g = 0; g < 2; g++) {
        mma_gemm_nt<3, false, false, true><<<gQKV, 256, SM3>>>(
            p_xh, p_xl, DD, p_wqh + (2 + g) * QS_ * DD, p_wql + (2 + g) * QS_ * DD, DD,
            p_bp + (2 + g) * QS_, nullptr, 0, DD, 1.f, DD, 0);
        mma_gemm_nt<1, false, true, false><<<gScore, 256, SM1>>>(
            p_qh, nb, DD, p_kh, nb, DD,
            nf, p_Sb, NN_, DD, inv_sqrt_dh, DD, 0);
        softmax_glob_bf16<<<NN_, 256>>>(cid);
        mma_gemm_nt<1, true, false, false><<<gPV, 256, SM1>>>(
            p_Sb, nb, NN_, p_vth, nb, NN_,
            nf, p_slab, DD, NN_, 1.f, NN_ / 2, (size_t)NN_ * DD);
        reduce_pv_split<<<NN_ * DD / 256, 256>>>();
        mma_gemm_nt<3, true, false, false><<<gProj, 256, SM3>>>(
            p_xh, p_xl, DD, p_owh + (2 + g) * DD * DD, p_owl + (2 + g) * DD * DD, DD,
            nf, p_slab, DD, DD, 1.f, 128, (size_t)NN_ * DD);
        ln_res_f<<<NN_ / 8, 256>>>(glob_g + g * DD, glob_b + g * DD,
                                   nf, glob_ob + g * DD);
    }

    // ---- output projection (3-pass, fused bias) ----
    mma_gemm_nt<3, false, false, false><<<gOut, 256, SM3>>>(
        p_xh, p_xl, DD, p_outwh, p_outwl, DD,
        out_b, out, OD, DD, 1.f, DD, 0);
}